// round 1
// baseline (speedup 1.0000x reference)
#include <cuda_runtime.h>
#include <cstdint>
#include <math.h>

#define N_NODES 50000
#define N_EDGES 800000
#define D_IN 8
#define D 128

// ---- scratch (static device globals; no allocation) ----
__device__ __align__(128) float g_bufX[N_NODES * D];   // hx -> h2
__device__ __align__(128) float g_bufH1[N_NODES * D];  // h1 -> A
__device__ __align__(128) float g_bufG[N_NODES * D];   // g  -> B
__device__ float g_dinv[N_NODES];
__device__ int   g_cnt[N_NODES];
__device__ int   g_off[N_NODES + 1];
__device__ int   g_cur[N_NODES];
__device__ int   g_srcs[N_EDGES];
__device__ float g_ws[N_EDGES];

// ---- CSR build: count incoming edges per dst ----
__global__ void k_zero_cnt() {
    int i = blockIdx.x * blockDim.x + threadIdx.x;
    if (i < N_NODES) g_cnt[i] = 0;
}

__global__ void k_count(const int* __restrict__ dst) {
    int e = blockIdx.x * blockDim.x + threadIdx.x;
    if (e < N_EDGES) atomicAdd(&g_cnt[dst[e]], 1);
}

// single-block prefix sum over 50000 counts; also emits dinv and cursor
__global__ void k_scan() {
    __shared__ int sdata[1024];
    __shared__ int s_carry;
    int tid = threadIdx.x;
    if (tid == 0) { s_carry = 0; g_off[0] = 0; }
    __syncthreads();
    for (int base = 0; base < N_NODES; base += 1024) {
        int i = base + tid;
        int v = (i < N_NODES) ? g_cnt[i] : 0;
        sdata[tid] = v;
        __syncthreads();
        for (int off = 1; off < 1024; off <<= 1) {
            int t = (tid >= off) ? sdata[tid - off] : 0;
            __syncthreads();
            sdata[tid] += t;
            __syncthreads();
        }
        int incl = sdata[tid];
        int carry = s_carry;
        if (i < N_NODES) {
            g_off[i + 1] = carry + incl;
            g_cur[i]     = carry + incl - v;          // exclusive
            g_dinv[i]    = rsqrtf((float)v + 1.0f);   // deg = cnt + 1 (self-loop)
        }
        __syncthreads();
        if (tid == 1023) s_carry = carry + sdata[1023];
        __syncthreads();
    }
}

// scatter edges into dst-grouped lists with precomputed norm = dinv[s]*dinv[d]
__global__ void k_fill(const int* __restrict__ src, const int* __restrict__ dst) {
    int e = blockIdx.x * blockDim.x + threadIdx.x;
    if (e >= N_EDGES) return;
    int s = src[e], d = dst[e];
    int p = atomicAdd(&g_cur[d], 1);
    g_srcs[p] = s;
    g_ws[p]   = g_dinv[s] * g_dinv[d];
}

// ---- layer-1 input GEMM: hx = x[50000,8] @ W1[8,128] ----
__global__ void k_gemm_in(const float* __restrict__ x, const float* __restrict__ W1) {
    int node = blockIdx.x * 2 + (threadIdx.x >> 7);
    int j = threadIdx.x & 127;
    if (node >= N_NODES) return;
    float s = 0.f;
#pragma unroll
    for (int k = 0; k < D_IN; k++)
        s = fmaf(x[node * D_IN + k], W1[k * D + j], s);
    g_bufX[node * D + j] = s;
}

// ---- normalized aggregation + bias + relu (gather form, no atomics) ----
__global__ void k_aggregate(const float* __restrict__ Hin, const float* __restrict__ bias,
                            float* __restrict__ Hout) {
    int n = blockIdx.x;
    int j = threadIdx.x; // 128 threads
    float di = g_dinv[n];
    float acc = Hin[n * D + j] * di * di;  // self-loop term
    int i0 = g_off[n], i1 = g_off[n + 1];
    for (int i = i0; i < i1; i++) {
        acc = fmaf(Hin[g_srcs[i] * D + j], g_ws[i], acc);
    }
    Hout[n * D + j] = fmaxf(acc + bias[j], 0.f);
}

// ---- dense C[M,128] = H[M,128] @ W[128,128] (+bias) ----
// 256 threads, 64 rows/block; W fully in smem; 8x4 register tile per thread.
__global__ void k_gemm128(const float* __restrict__ H, const float* __restrict__ W,
                          const float* __restrict__ bias, float* __restrict__ C) {
    extern __shared__ float smem[];
    float* Ws = smem;          // 128*128
    float* Hs = smem + D * D;  // 64*128
    int tid = threadIdx.x;
    for (int i = tid * 4; i < D * D; i += 256 * 4)
        *(float4*)&Ws[i] = *(const float4*)&W[i];
    int row0 = blockIdx.x * 64;
    for (int i = tid * 4; i < 64 * D; i += 256 * 4) {
        int r = row0 + (i >> 7);
        float4 v = make_float4(0.f, 0.f, 0.f, 0.f);
        if (r < N_NODES) v = *(const float4*)&H[r * D + (i & 127)];
        *(float4*)&Hs[i] = v;
    }
    __syncthreads();
    int warp = tid >> 5, lane = tid & 31;
    float acc[8][4];
#pragma unroll
    for (int n = 0; n < 8; n++) { acc[n][0] = acc[n][1] = acc[n][2] = acc[n][3] = 0.f; }
    const float* hrow = &Hs[warp * 8 * D];
#pragma unroll 4
    for (int k = 0; k < D; k++) {
        float4 w = *(float4*)&Ws[k * D + lane * 4];
#pragma unroll
        for (int n = 0; n < 8; n++) {
            float h = hrow[n * D + k];
            acc[n][0] = fmaf(h, w.x, acc[n][0]);
            acc[n][1] = fmaf(h, w.y, acc[n][1]);
            acc[n][2] = fmaf(h, w.z, acc[n][2]);
            acc[n][3] = fmaf(h, w.w, acc[n][3]);
        }
    }
    float4 bv = make_float4(0.f, 0.f, 0.f, 0.f);
    if (bias) bv = *(const float4*)&bias[lane * 4];
#pragma unroll
    for (int n = 0; n < 8; n++) {
        int r = row0 + warp * 8 + n;
        if (r < N_NODES) {
            float4 o = make_float4(acc[n][0] + bv.x, acc[n][1] + bv.y,
                                   acc[n][2] + bv.z, acc[n][3] + bv.w);
            *(float4*)&C[r * D + lane * 4] = o;
        }
    }
}

// ---- per-edge head: v = relu(A[src]+B[dst]); logits = v@Wfin + bfin; log_softmax ----
__global__ void k_edge_out(const int* __restrict__ src, const int* __restrict__ dst,
                           const float* __restrict__ A, const float* __restrict__ B,
                           const float* __restrict__ Wfin, const float* __restrict__ bfin,
                           float* __restrict__ out) {
    int gid = blockIdx.x * blockDim.x + threadIdx.x;
    int e = gid >> 5;
    int lane = gid & 31;
    if (e >= N_EDGES) return;
    int s = src[e], d = dst[e];
    float4 a = *(const float4*)&A[s * D + lane * 4];
    float4 b = *(const float4*)&B[d * D + lane * 4];
    float v0 = fmaxf(a.x + b.x, 0.f);
    float v1 = fmaxf(a.y + b.y, 0.f);
    float v2 = fmaxf(a.z + b.z, 0.f);
    float v3 = fmaxf(a.w + b.w, 0.f);
    // Wfin row-major [128,2]: rows (4*lane .. 4*lane+3) -> 8 consecutive floats
    float4 w01 = *(const float4*)&Wfin[lane * 8];
    float4 w23 = *(const float4*)&Wfin[lane * 8 + 4];
    float l0 = v0 * w01.x + v1 * w01.z + v2 * w23.x + v3 * w23.z;
    float l1 = v0 * w01.y + v1 * w01.w + v2 * w23.y + v3 * w23.w;
#pragma unroll
    for (int o = 16; o; o >>= 1) {
        l0 += __shfl_xor_sync(0xffffffffu, l0, o);
        l1 += __shfl_xor_sync(0xffffffffu, l1, o);
    }
    if (lane == 0) {
        l0 += bfin[0];
        l1 += bfin[1];
        float m = fmaxf(l0, l1);
        float lse = m + logf(expf(l0 - m) + expf(l1 - m));
        out[2 * e]     = l0 - lse;
        out[2 * e + 1] = l1 - lse;
    }
}

extern "C" void kernel_launch(void* const* d_in, const int* in_sizes, int n_in,
                              void* d_out, int out_size) {
    const float* x     = (const float*)d_in[0];
    const int*   ei    = (const int*)d_in[1];
    const float* W1    = (const float*)d_in[2];
    const float* b1    = (const float*)d_in[3];
    const float* W2    = (const float*)d_in[4];
    const float* b2    = (const float*)d_in[5];
    const float* Wlin1 = (const float*)d_in[6];
    const float* blin1 = (const float*)d_in[7];
    const float* Wfin  = (const float*)d_in[8];
    const float* bfin  = (const float*)d_in[9];
    const int* src = ei;
    const int* dst = ei + N_EDGES;
    float* out = (float*)d_out;

    void *pX, *pH1, *pG;
    cudaGetSymbolAddress(&pX, g_bufX);
    cudaGetSymbolAddress(&pH1, g_bufH1);
    cudaGetSymbolAddress(&pG, g_bufG);
    float* bufX  = (float*)pX;
    float* bufH1 = (float*)pH1;
    float* bufG  = (float*)pG;

    const int gemm_smem = (D * D + 64 * D) * 4;  // 96 KB
    cudaFuncSetAttribute(k_gemm128, cudaFuncAttributeMaxDynamicSharedMemorySize, gemm_smem);

    // graph structure (rebuilt every call; deterministic math)
    k_zero_cnt<<<(N_NODES + 255) / 256, 256>>>();
    k_count<<<(N_EDGES + 255) / 256, 256>>>(dst);
    k_scan<<<1, 1024>>>();
    k_fill<<<(N_EDGES + 255) / 256, 256>>>(src, dst);

    // layer 1
    k_gemm_in<<<N_NODES / 2, 256>>>(x, W1);                               // hx = x@W1 -> bufX
    k_aggregate<<<N_NODES, 128>>>(bufX, b1, bufH1);                       // h1 -> bufH1

    // layer 2
    k_gemm128<<<(N_NODES + 63) / 64, 256, gemm_smem>>>(bufH1, W2, nullptr, bufG);  // g -> bufG
    k_aggregate<<<N_NODES, 128>>>(bufG, b2, bufX);                        // h2 -> bufX

    // per-node halves of the edge MLP (concat trick)
    k_gemm128<<<(N_NODES + 63) / 64, 256, gemm_smem>>>(bufX, Wlin1, blin1, bufH1);        // A
    k_gemm128<<<(N_NODES + 63) / 64, 256, gemm_smem>>>(bufX, Wlin1 + D * D, nullptr, bufG); // B

    // per-edge head
    k_edge_out<<<(N_EDGES + 7) / 8, 256>>>(src, dst, bufH1, bufG, Wfin, bfin, out);
}

// round 2
// speedup vs baseline: 1.1004x; 1.1004x over previous
#include <cuda_runtime.h>
#include <cstdint>
#include <math.h>

#define N_NODES 50000
#define N_EDGES 800000
#define D_IN 8
#define D 128

// ---- scratch (static device globals; no allocation) ----
__device__ __align__(128) float g_bufX[N_NODES * D];   // hx -> h2
__device__ __align__(128) float g_bufH1[N_NODES * D];  // h1 -> A
__device__ __align__(128) float g_bufG[N_NODES * D];   // g  -> B
__device__ float g_dinv[N_NODES];
__device__ int   g_cnt[N_NODES];
__device__ int   g_off[N_NODES + 1];
__device__ int   g_cur[N_NODES];
__device__ int   g_srcs[N_EDGES];
__device__ float g_ws[N_EDGES];

// ---- packed f32x2 helpers ----
__device__ __forceinline__ unsigned long long pack2(float lo, float hi) {
    unsigned long long r;
    asm("mov.b64 %0, {%1, %2};" : "=l"(r) : "f"(lo), "f"(hi));
    return r;
}
__device__ __forceinline__ void fma2(unsigned long long& acc, unsigned long long a,
                                     unsigned long long b) {
    asm("fma.rn.f32x2 %0, %1, %2, %3;" : "=l"(acc) : "l"(a), "l"(b), "l"(acc));
}
__device__ __forceinline__ float2 unpack2(unsigned long long v) {
    float2 r;
    asm("mov.b64 {%0, %1}, %2;" : "=f"(r.x), "=f"(r.y) : "l"(v));
    return r;
}

// ---- CSR build ----
__global__ void k_zero_cnt() {
    int i = blockIdx.x * blockDim.x + threadIdx.x;
    if (i < N_NODES) g_cnt[i] = 0;
}

__global__ void k_count(const int* __restrict__ dst) {
    int e = blockIdx.x * blockDim.x + threadIdx.x;
    if (e < N_EDGES) atomicAdd(&g_cnt[dst[e]], 1);
}

// thread-coarsened single-block scan: 1024 threads x ~49 elems each
__global__ void k_scan() {
    __shared__ int warp_sums[32];
    const int CH = (N_NODES + 1023) / 1024;  // 49
    int tid = threadIdx.x;
    int lane = tid & 31, wid = tid >> 5;
    int start = tid * CH;
    int end = min(start + CH, N_NODES);
    int sum = 0;
    for (int i = start; i < end; i++) sum += g_cnt[i];
    // inclusive scan of per-thread sums
    int v = sum;
#pragma unroll
    for (int o = 1; o < 32; o <<= 1) {
        int t = __shfl_up_sync(0xffffffffu, v, o);
        if (lane >= o) v += t;
    }
    if (lane == 31) warp_sums[wid] = v;
    __syncthreads();
    if (wid == 0) {
        int s = warp_sums[lane];
#pragma unroll
        for (int o = 1; o < 32; o <<= 1) {
            int t = __shfl_up_sync(0xffffffffu, s, o);
            if (lane >= o) s += t;
        }
        warp_sums[lane] = s;
    }
    __syncthreads();
    int run = v - sum + (wid > 0 ? warp_sums[wid - 1] : 0);  // exclusive prefix
    for (int i = start; i < end; i++) {
        int c = g_cnt[i];
        g_cur[i] = run;
        run += c;
        g_off[i + 1] = run;
        g_dinv[i] = rsqrtf((float)c + 1.0f);  // deg = cnt + 1 (self-loop)
    }
    if (tid == 0) g_off[0] = 0;
}

__global__ void k_fill(const int* __restrict__ src, const int* __restrict__ dst) {
    int e = blockIdx.x * blockDim.x + threadIdx.x;
    if (e >= N_EDGES) return;
    int s = src[e], d = dst[e];
    int p = atomicAdd(&g_cur[d], 1);
    g_srcs[p] = s;
    g_ws[p]   = g_dinv[s] * g_dinv[d];
}

// ---- layer-1 input GEMM: hx = x[50000,8] @ W1[8,128] ----
__global__ void k_gemm_in(const float* __restrict__ x, const float* __restrict__ W1) {
    int node = blockIdx.x * 2 + (threadIdx.x >> 7);
    int j = threadIdx.x & 127;
    if (node >= N_NODES) return;
    float s = 0.f;
#pragma unroll
    for (int k = 0; k < D_IN; k++)
        s = fmaf(x[node * D_IN + k], W1[k * D + j], s);
    g_bufX[node * D + j] = s;
}

// ---- normalized aggregation + bias + relu: warp per node, float4 lanes ----
__global__ void k_aggregate(const float* __restrict__ Hin, const float* __restrict__ bias,
                            float* __restrict__ Hout) {
    int n = (blockIdx.x * blockDim.x + threadIdx.x) >> 5;
    int lane = threadIdx.x & 31;
    if (n >= N_NODES) return;
    float di = g_dinv[n];
    float wself = di * di;
    float4 self = *(const float4*)&Hin[n * D + lane * 4];
    float4 acc = make_float4(self.x * wself, self.y * wself, self.z * wself, self.w * wself);
    int i0 = g_off[n], i1 = g_off[n + 1];
    int i = i0;
    for (; i + 2 <= i1; i += 2) {
        int s0 = g_srcs[i], s1 = g_srcs[i + 1];
        float w0 = g_ws[i], w1 = g_ws[i + 1];
        float4 v0 = *(const float4*)&Hin[s0 * D + lane * 4];
        float4 v1 = *(const float4*)&Hin[s1 * D + lane * 4];
        acc.x = fmaf(v0.x, w0, acc.x); acc.y = fmaf(v0.y, w0, acc.y);
        acc.z = fmaf(v0.z, w0, acc.z); acc.w = fmaf(v0.w, w0, acc.w);
        acc.x = fmaf(v1.x, w1, acc.x); acc.y = fmaf(v1.y, w1, acc.y);
        acc.z = fmaf(v1.z, w1, acc.z); acc.w = fmaf(v1.w, w1, acc.w);
    }
    if (i < i1) {
        int s0 = g_srcs[i];
        float w0 = g_ws[i];
        float4 v0 = *(const float4*)&Hin[s0 * D + lane * 4];
        acc.x = fmaf(v0.x, w0, acc.x); acc.y = fmaf(v0.y, w0, acc.y);
        acc.z = fmaf(v0.z, w0, acc.z); acc.w = fmaf(v0.w, w0, acc.w);
    }
    float4 bv = *(const float4*)&bias[lane * 4];
    float4 o = make_float4(fmaxf(acc.x + bv.x, 0.f), fmaxf(acc.y + bv.y, 0.f),
                           fmaxf(acc.z + bv.z, 0.f), fmaxf(acc.w + bv.w, 0.f));
    *(float4*)&Hout[n * D + lane * 4] = o;
}

// ---- dense C[M,128] = H[M,128] @ W[128,128] (+bias), packed f32x2 FMA ----
// 256 threads, 64 rows/block; W in smem; per thread: 8 rows x 4 cols (2 f32x2 pairs).
__global__ void __launch_bounds__(256) k_gemm128(
    const float* __restrict__ H, const float* __restrict__ W,
    const float* __restrict__ bias, float* __restrict__ C) {
    extern __shared__ float smem[];
    float* Ws = smem;          // 128*128
    float* Hs = smem + D * D;  // 64*128
    int tid = threadIdx.x;
    for (int i = tid * 4; i < D * D; i += 256 * 4)
        *(float4*)&Ws[i] = *(const float4*)&W[i];
    int row0 = blockIdx.x * 64;
    for (int i = tid * 4; i < 64 * D; i += 256 * 4) {
        int r = row0 + (i >> 7);
        float4 v = make_float4(0.f, 0.f, 0.f, 0.f);
        if (r < N_NODES) v = *(const float4*)&H[r * D + (i & 127)];
        *(float4*)&Hs[i] = v;
    }
    __syncthreads();
    int warp = tid >> 5, lane = tid & 31;
    unsigned long long acc01[8], acc23[8];
#pragma unroll
    for (int n = 0; n < 8; n++) { acc01[n] = 0ull; acc23[n] = 0ull; }
    const float* hrow = &Hs[warp * 8 * D];

    for (int k0 = 0; k0 < D; k0 += 4) {
        float4 hreg[8];
#pragma unroll
        for (int n = 0; n < 8; n++)
            hreg[n] = *(const float4*)&hrow[n * D + k0];
#pragma unroll
        for (int kk = 0; kk < 4; kk++) {
            float4 w = *(const float4*)&Ws[(k0 + kk) * D + lane * 4];
            unsigned long long w01 = pack2(w.x, w.y);
            unsigned long long w23 = pack2(w.z, w.w);
#pragma unroll
            for (int n = 0; n < 8; n++) {
                float h = (kk == 0) ? hreg[n].x : (kk == 1) ? hreg[n].y
                         : (kk == 2) ? hreg[n].z : hreg[n].w;
                unsigned long long h2 = pack2(h, h);
                fma2(acc01[n], h2, w01);
                fma2(acc23[n], h2, w23);
            }
        }
    }
    float4 bv = make_float4(0.f, 0.f, 0.f, 0.f);
    if (bias) bv = *(const float4*)&bias[lane * 4];
#pragma unroll
    for (int n = 0; n < 8; n++) {
        int r = row0 + warp * 8 + n;
        if (r < N_NODES) {
            float2 p01 = unpack2(acc01[n]);
            float2 p23 = unpack2(acc23[n]);
            float4 o = make_float4(p01.x + bv.x, p01.y + bv.y, p23.x + bv.z, p23.y + bv.w);
            *(float4*)&C[r * D + lane * 4] = o;
        }
    }
}

// ---- per-edge head: v = relu(A[src]+B[dst]); logits = v@Wfin + bfin; log_softmax ----
__global__ void k_edge_out(const int* __restrict__ src, const int* __restrict__ dst,
                           const float* __restrict__ A, const float* __restrict__ B,
                           const float* __restrict__ Wfin, const float* __restrict__ bfin,
                           float* __restrict__ out) {
    int gid = blockIdx.x * blockDim.x + threadIdx.x;
    int e = gid >> 5;
    int lane = gid & 31;
    if (e >= N_EDGES) return;
    int s = src[e], d = dst[e];
    float4 a = *(const float4*)&A[s * D + lane * 4];
    float4 b = *(const float4*)&B[d * D + lane * 4];
    float v0 = fmaxf(a.x + b.x, 0.f);
    float v1 = fmaxf(a.y + b.y, 0.f);
    float v2 = fmaxf(a.z + b.z, 0.f);
    float v3 = fmaxf(a.w + b.w, 0.f);
    // Wfin row-major [128,2]: rows (4*lane .. 4*lane+3) -> 8 consecutive floats
    float4 w01 = *(const float4*)&Wfin[lane * 8];
    float4 w23 = *(const float4*)&Wfin[lane * 8 + 4];
    float l0 = v0 * w01.x + v1 * w01.z + v2 * w23.x + v3 * w23.z;
    float l1 = v0 * w01.y + v1 * w01.w + v2 * w23.y + v3 * w23.w;
#pragma unroll
    for (int o = 16; o; o >>= 1) {
        l0 += __shfl_xor_sync(0xffffffffu, l0, o);
        l1 += __shfl_xor_sync(0xffffffffu, l1, o);
    }
    if (lane == 0) {
        l0 += bfin[0];
        l1 += bfin[1];
        float m = fmaxf(l0, l1);
        float lse = m + __logf(__expf(l0 - m) + __expf(l1 - m));
        out[2 * e]     = l0 - lse;
        out[2 * e + 1] = l1 - lse;
    }
}

extern "C" void kernel_launch(void* const* d_in, const int* in_sizes, int n_in,
                              void* d_out, int out_size) {
    const float* x     = (const float*)d_in[0];
    const int*   ei    = (const int*)d_in[1];
    const float* W1    = (const float*)d_in[2];
    const float* b1    = (const float*)d_in[3];
    const float* W2    = (const float*)d_in[4];
    const float* b2    = (const float*)d_in[5];
    const float* Wlin1 = (const float*)d_in[6];
    const float* blin1 = (const float*)d_in[7];
    const float* Wfin  = (const float*)d_in[8];
    const float* bfin  = (const float*)d_in[9];
    const int* src = ei;
    const int* dst = ei + N_EDGES;
    float* out = (float*)d_out;

    void *pX, *pH1, *pG;
    cudaGetSymbolAddress(&pX, g_bufX);
    cudaGetSymbolAddress(&pH1, g_bufH1);
    cudaGetSymbolAddress(&pG, g_bufG);
    float* bufX  = (float*)pX;
    float* bufH1 = (float*)pH1;
    float* bufG  = (float*)pG;

    const int gemm_smem = (D * D + 64 * D) * 4;  // 96 KB
    cudaFuncSetAttribute(k_gemm128, cudaFuncAttributeMaxDynamicSharedMemorySize, gemm_smem);

    // graph structure (rebuilt every call; deterministic math)
    k_zero_cnt<<<(N_NODES + 255) / 256, 256>>>();
    k_count<<<(N_EDGES + 255) / 256, 256>>>(dst);
    k_scan<<<1, 1024>>>();
    k_fill<<<(N_EDGES + 255) / 256, 256>>>(src, dst);

    // layer 1
    k_gemm_in<<<N_NODES / 2, 256>>>(x, W1);                               // hx = x@W1 -> bufX
    k_aggregate<<<(N_NODES * 32 + 255) / 256, 256>>>(bufX, b1, bufH1);    // h1 -> bufH1

    // layer 2
    k_gemm128<<<(N_NODES + 63) / 64, 256, gemm_smem>>>(bufH1, W2, nullptr, bufG);  // g -> bufG
    k_aggregate<<<(N_NODES * 32 + 255) / 256, 256>>>(bufG, b2, bufX);     // h2 -> bufX

    // per-node halves of the edge MLP (concat trick)
    k_gemm128<<<(N_NODES + 63) / 64, 256, gemm_smem>>>(bufX, Wlin1, blin1, bufH1);          // A
    k_gemm128<<<(N_NODES + 63) / 64, 256, gemm_smem>>>(bufX, Wlin1 + D * D, nullptr, bufG); // B

    // per-edge head
    k_edge_out<<<(N_EDGES + 7) / 8, 256>>>(src, dst, bufH1, bufG, Wfin, bfin, out);
}